// round 2
// baseline (speedup 1.0000x reference)
#include <cuda_runtime.h>

#define N_NODES 100000
#define N_EDGES 3200000
#define R0 16
#define R1 8
#define R2 16
#define N1 32

// ---------------- scratch (device globals; no allocation allowed) ----------------
__device__ __align__(16) float g_y1[N_NODES * R1];    // x @ W_rel1
__device__ __align__(16) float g_r1[N_NODES * R1];    // x @ W_root1 + b_rel1
__device__ __align__(16) float g_agg1[N_NODES * R1];  // segment_sum layer 1 (transformed space)
__device__ __align__(16) float g_h1[N_NODES * R1];    // relu(agg1 + r1)
__device__ __align__(16) float g_agg2[N_NODES * R1];  // segment_sum layer 2
__device__ double g_sum;

// vector reduction: one L2 op covers 16B (4 floats)
__device__ __forceinline__ void red_add_v4(float* p, float4 v) {
    asm volatile("red.global.add.v4.f32 [%0], {%1, %2, %3, %4};"
                 :: "l"(p), "f"(v.x), "f"(v.y), "f"(v.z), "f"(v.w)
                 : "memory");
}

// ---------------- K0: zero accumulators ----------------
__global__ void k_zero() {
    int i = blockIdx.x * blockDim.x + threadIdx.x;
    const int n4 = N_NODES * R1 / 4;  // 200000 float4 per buffer
    float4 z = make_float4(0.f, 0.f, 0.f, 0.f);
    if (i < n4) {
        reinterpret_cast<float4*>(g_agg1)[i] = z;
        reinterpret_cast<float4*>(g_agg2)[i] = z;
    }
    if (i == 0) g_sum = 0.0;
}

// ---------------- K1: per-node pre-transform for layer 1 ----------------
// y1 = x @ W_rel1 ; r1 = x @ W_root1 + b_rel1
__global__ void k_node1(const float* __restrict__ x,
                        const float* __restrict__ Wrel,
                        const float* __restrict__ brel,
                        const float* __restrict__ Wroot) {
    __shared__ float sWr[R0 * R1];
    __shared__ float sWo[R0 * R1];
    __shared__ float sb[R1];
    int t = threadIdx.x;
    if (t < R0 * R1) { sWr[t] = Wrel[t]; sWo[t] = Wroot[t]; }
    if (t < R1) sb[t] = brel[t];
    __syncthreads();

    int i = blockIdx.x * blockDim.x + t;
    if (i >= N_NODES) return;

    float xr[R0];
    const float4* xp = reinterpret_cast<const float4*>(x + (size_t)i * R0);
#pragma unroll
    for (int q = 0; q < R0 / 4; q++) {
        float4 v = xp[q];
        xr[4 * q + 0] = v.x; xr[4 * q + 1] = v.y;
        xr[4 * q + 2] = v.z; xr[4 * q + 3] = v.w;
    }

    float y[R1], r[R1];
#pragma unroll
    for (int k = 0; k < R1; k++) { y[k] = 0.f; r[k] = sb[k]; }
#pragma unroll
    for (int j = 0; j < R0; j++) {
        float xj = xr[j];
#pragma unroll
        for (int k = 0; k < R1; k++) {
            y[k] += xj * sWr[j * R1 + k];
            r[k] += xj * sWo[j * R1 + k];
        }
    }

    float4* yp = reinterpret_cast<float4*>(g_y1 + (size_t)i * R1);
    float4* rp = reinterpret_cast<float4*>(g_r1 + (size_t)i * R1);
    yp[0] = make_float4(y[0], y[1], y[2], y[3]);
    yp[1] = make_float4(y[4], y[5], y[6], y[7]);
    rp[0] = make_float4(r[0], r[1], r[2], r[3]);
    rp[1] = make_float4(r[4], r[5], r[6], r[7]);
}

// ---------------- K2/K4: edge gather + scatter-add (width 8) ----------------
// edge_index is int32 (JAX default config demotes int64 -> int32).
__global__ void k_edge(const int* __restrict__ ei, int layer) {
    const float* __restrict__ srcbuf = (layer == 1) ? g_y1 : g_h1;
    float* dstbuf = (layer == 1) ? g_agg1 : g_agg2;

    int e = blockIdx.x * blockDim.x + threadIdx.x;
    if (e >= N_EDGES) return;

    int s = ei[e];
    int d = ei[N_EDGES + e];

    const float4* sp = reinterpret_cast<const float4*>(srcbuf + (size_t)s * R1);
    float4 a = __ldg(sp);
    float4 b = __ldg(sp + 1);

    float* dp = dstbuf + (size_t)d * R1;
    red_add_v4(dp, a);
    red_add_v4(dp + 4, b);
}

// ---------------- K3: h1 = relu(agg1 + r1) ----------------
__global__ void k_relu1() {
    int i = blockIdx.x * blockDim.x + threadIdx.x;
    const int n4 = N_NODES * R1 / 4;
    if (i >= n4) return;
    float4 a = reinterpret_cast<const float4*>(g_agg1)[i];
    float4 r = reinterpret_cast<const float4*>(g_r1)[i];
    float4 h;
    h.x = fmaxf(a.x + r.x, 0.f);
    h.y = fmaxf(a.y + r.y, 0.f);
    h.z = fmaxf(a.z + r.z, 0.f);
    h.w = fmaxf(a.w + r.w, 0.f);
    reinterpret_cast<float4*>(g_h1)[i] = h;
}

// ---------------- K5: fused conv2 + fc1 + fc2 + sum reduce ----------------
__global__ void k_node2(const float* __restrict__ Wrel2,
                        const float* __restrict__ brel2,
                        const float* __restrict__ Wroot2,
                        const float* __restrict__ Wfc1,
                        const float* __restrict__ bfc1,
                        const float* __restrict__ Wfc2,
                        const float* __restrict__ bfc2,
                        float* __restrict__ out) {
    __shared__ float sWr[R1 * R2];   // 128
    __shared__ float sWo[R1 * R2];   // 128
    __shared__ float sb2[R2];        // 16
    __shared__ float sF1[R2 * N1];   // 512
    __shared__ float sb3[N1];        // 32
    __shared__ float sF2[N1];        // 32
    __shared__ float sbf2;

    int t = threadIdx.x;
    for (int j = t; j < R1 * R2; j += blockDim.x) { sWr[j] = Wrel2[j]; sWo[j] = Wroot2[j]; }
    for (int j = t; j < R2 * N1; j += blockDim.x) sF1[j] = Wfc1[j];
    if (t < R2) sb2[t] = brel2[t];
    if (t < N1) { sb3[t] = bfc1[t]; sF2[t] = Wfc2[t]; }
    if (t == 0) sbf2 = bfc2[0];
    __syncthreads();

    int i = blockIdx.x * blockDim.x + t;
    float o = 0.f;
    if (i < N_NODES) {
        float a[R1], h[R1];
        const float4* ap = reinterpret_cast<const float4*>(g_agg2 + (size_t)i * R1);
        const float4* hp = reinterpret_cast<const float4*>(g_h1 + (size_t)i * R1);
        float4 v;
        v = ap[0]; a[0] = v.x; a[1] = v.y; a[2] = v.z; a[3] = v.w;
        v = ap[1]; a[4] = v.x; a[5] = v.y; a[6] = v.z; a[7] = v.w;
        v = hp[0]; h[0] = v.x; h[1] = v.y; h[2] = v.z; h[3] = v.w;
        v = hp[1]; h[4] = v.x; h[5] = v.y; h[6] = v.z; h[7] = v.w;

        float h2[R2];
#pragma unroll
        for (int k = 0; k < R2; k++) h2[k] = sb2[k];
#pragma unroll
        for (int j = 0; j < R1; j++) {
            float aj = a[j], hj = h[j];
#pragma unroll
            for (int k = 0; k < R2; k++)
                h2[k] += aj * sWr[j * R2 + k] + hj * sWo[j * R2 + k];
        }
#pragma unroll
        for (int k = 0; k < R2; k++) h2[k] = fmaxf(h2[k], 0.f);

        o = sbf2;
#pragma unroll
        for (int m = 0; m < N1; m++) {
            float acc = sb3[m];
#pragma unroll
            for (int k = 0; k < R2; k++) acc += h2[k] * sF1[k * N1 + m];
            o += fmaxf(acc, 0.f) * sF2[m];
        }
        out[i] = o;
    }

    // warp reduce o, one double atomic per warp
    float v2 = (i < N_NODES) ? o : 0.f;
#pragma unroll
    for (int off = 16; off > 0; off >>= 1)
        v2 += __shfl_down_sync(0xffffffffu, v2, off);
    if ((t & 31) == 0) atomicAdd(&g_sum, (double)v2);
}

// ---------------- K6: subtract mean ----------------
__global__ void k_mean(float* __restrict__ out) {
    int i = blockIdx.x * blockDim.x + threadIdx.x;
    if (i >= N_NODES) return;
    float m = (float)(g_sum / (double)N_NODES);
    out[i] -= m;
}

// ---------------- launch ----------------
extern "C" void kernel_launch(void* const* d_in, const int* in_sizes, int n_in,
                              void* d_out, int out_size) {
    const float* x      = (const float*)d_in[0];
    const int*   ei     = (const int*)d_in[1];
    const float* Wrel1  = (const float*)d_in[2];
    const float* brel1  = (const float*)d_in[3];
    const float* Wroot1 = (const float*)d_in[4];
    const float* Wrel2  = (const float*)d_in[5];
    const float* brel2  = (const float*)d_in[6];
    const float* Wroot2 = (const float*)d_in[7];
    const float* Wfc1   = (const float*)d_in[8];
    const float* bfc1   = (const float*)d_in[9];
    const float* Wfc2   = (const float*)d_in[10];
    const float* bfc2   = (const float*)d_in[11];
    float* out = (float*)d_out;

    const int n4 = N_NODES * R1 / 4;  // 200000

    k_zero<<<(n4 + 255) / 256, 256>>>();
    k_node1<<<(N_NODES + 127) / 128, 128>>>(x, Wrel1, brel1, Wroot1);
    k_edge<<<(N_EDGES + 255) / 256, 256>>>(ei, 1);
    k_relu1<<<(n4 + 255) / 256, 256>>>();
    k_edge<<<(N_EDGES + 255) / 256, 256>>>(ei, 2);
    k_node2<<<(N_NODES + 255) / 256, 256>>>(Wrel2, brel2, Wroot2,
                                            Wfc1, bfc1, Wfc2, bfc2, out);
    k_mean<<<(N_NODES + 255) / 256, 256>>>(out);
}